// round 5
// baseline (speedup 1.0000x reference)
#include <cuda_runtime.h>
#include <cstdint>

// Problem constants
#define RR 4
#define ND 81
#define NB 4
#define NC 128
#define NH 96
#define NW 160

// Tiling
#define TX 32
#define YB 8
#define PX 8
#define XG 4                  // TX/PX
#define NDY 9
#define NTHREADS 288          // 9 warps
#define CCHUNK 8
#define NCHUNK 16
#define TGT_REAL 40           // TX + 2*RR
#define TGT_W 44              // padded: 176B ≡ 48 (mod 128) -> alt-parity rows conflict-free
#define TGT_H 16              // YB + 2*RR
#define TGT_TILE (CCHUNK*TGT_H*TGT_W)    // 5632 floats
#define SRC_TILE (CCHUNK*YB*TX)          // 2048 floats
#define BUF_FLOATS (TGT_TILE + SRC_TILE) // 7680
#define BUF_BYTES (BUF_FLOATS*4)         // 30720
#define SMEM_BYTES (3*BUF_BYTES)         // 92160
#define TGT_QUADS (CCHUNK*TGT_H*(TGT_REAL/4))  // 1280 (only real data staged)
#define NQUADS (TGT_QUADS + SRC_TILE/4)        // 1792
#define MAXSLOTS 7            // 6 full + 64-thread tail
#define CBYTES (CCHUNK*NH*NW*4)

typedef unsigned long long ull;

__device__ __forceinline__ int disp_index(int dyv, int dxv) {
    int ay = dyv < 0 ? -dyv : dyv;
    int ax = dxv < 0 ? -dxv : dxv;
    if ((ay | ax) == 0) return 0;
    if (ax == 0) return 1 + (ay - 1) * 20 + (dyv < 0 ? 0 : 1);
    if (ay == 0) return 1 + (ax - 1) * 20 + (dxv < 0 ? 2 : 3);
    int base = 1 + (ay - 1) * 20 + 4 + (ax - 1) * 4;
    if (dyv < 0 && dxv < 0) return base + 0;
    if (dyv > 0 && dxv > 0) return base + 1;
    if (dyv < 0 && dxv > 0) return base + 2;
    return base + 3;
}

__device__ __forceinline__ void cp_async16(uint32_t saddr, const void* gaddr, int sz) {
    asm volatile("cp.async.cg.shared.global [%0], [%1], 16, %2;\n"
                 :: "r"(saddr), "l"(gaddr), "r"(sz));
}
__device__ __forceinline__ void cp_commit() {
    asm volatile("cp.async.commit_group;\n" ::: "memory");
}
__device__ __forceinline__ ull pk2(float lo, float hi) {
    ull r;
    asm("mov.b64 %0, {%1, %2};" : "=l"(r) : "f"(lo), "f"(hi));
    return r;
}
__device__ __forceinline__ void upk2(ull v, float& lo, float& hi) {
    asm("mov.b64 {%0, %1}, %2;" : "=f"(lo), "=f"(hi) : "l"(v));
}
__device__ __forceinline__ void fma2(ull& d, ull a, ull b) {
    asm("fma.rn.f32x2 %0, %1, %2, %0;" : "+l"(d) : "l"(a), "l"(b));
}

__global__ __launch_bounds__(NTHREADS, 2)
void costvol_kernel(const float* __restrict__ src,
                    const float* __restrict__ tgt,
                    float* __restrict__ out) {
    extern __shared__ __align__(16) float sm[];   // 3 * BUF_FLOATS

    const int tid = threadIdx.x;
    const int x0 = blockIdx.x * TX;
    const int y0 = blockIdx.y * YB;
    const int b  = blockIdx.z;

    const char* srcB = (const char*)(src + (size_t)b * NC * NH * NW);
    const char* tgtB = (const char*)(tgt + (size_t)b * NC * NH * NW);

    // ---- staging slots (quad idx = tid + k*288; smem layout padded) ----
    uint32_t goff[MAXSLOTS];   // global byte offset (advances per chunk)
    uint32_t soff[MAXSLOTS];   // smem byte offset within buffer
    uint32_t flags = 0;        // bit k: tgt slot; bit k+8: in-bounds
#pragma unroll
    for (int k = 0; k < MAXSLOTS; k++) {
        int idx = tid + k * NTHREADS;
        goff[k] = 0; soff[k] = 0;
        if (idx < NQUADS) {
            if (idx < TGT_QUADS) {
                int cc  = idx / (TGT_H * (TGT_REAL / 4));   // /160
                int rem = idx % (TGT_H * (TGT_REAL / 4));
                int row = rem / (TGT_REAL / 4);             // /10
                int xq  = rem % (TGT_REAL / 4);
                int gy = y0 + row - RR;
                int gx = x0 + xq * 4 - RR;
                bool ok = ((unsigned)gy < NH) && ((unsigned)gx < NW);
                if (ok) goff[k] = (uint32_t)(((cc * NH + gy) * NW + gx) * 4);
                soff[k] = (uint32_t)((((cc * TGT_H + row) * TGT_W) + xq * 4) * 4);
                flags |= 1u << k;
                if (ok) flags |= 1u << (k + 8);
            } else {
                int q   = idx - TGT_QUADS;
                int cc  = q / (YB * TX / 4);                // /64
                int rem = q % (YB * TX / 4);
                int ry  = rem / (TX / 4);
                int xq  = rem % (TX / 4);
                goff[k] = (uint32_t)(((cc * NH + y0 + ry) * NW + x0 + xq * 4) * 4);
                soff[k] = (uint32_t)((TGT_TILE + (cc * YB + ry) * TX + xq * 4) * 4);
                flags |= 1u << (k + 8);
            }
        }
    }

    const uint32_t smem_base = (uint32_t)__cvta_generic_to_shared(&sm[0]);

    // ---- compute role ----
    const int xg   = tid & (XG - 1);
    const int dyi  = (tid >> 2) % NDY;
    const int yr   = tid / (XG * NDY);
    const int dyv  = dyi - RR;
    const int trow = yr + dyi;                            // 0..15
    const int t_off = trow * TGT_W + xg * PX;
    const int s_off = TGT_TILE + yr * TX + xg * PX;

    ull acc[NDY][4];
#pragma unroll
    for (int i = 0; i < NDY; i++)
#pragma unroll
        for (int j = 0; j < 4; j++) acc[i][j] = 0ull;

    auto stage = [&](int bi) {
        const uint32_t bofs = (uint32_t)bi * BUF_BYTES;
#pragma unroll
        for (int k = 0; k < MAXSLOTS; k++) {
            if (k < MAXSLOTS - 1 || tid < NQUADS - (MAXSLOTS - 1) * NTHREADS) {
                const char* base = (flags >> k & 1) ? tgtB : srcB;
                int sz = (flags >> (k + 8) & 1) ? 16 : 0;
                cp_async16(smem_base + bofs + soff[k], base + goff[k], sz);
                goff[k] += CBYTES;
            }
        }
        cp_commit();
    };

    stage(0);
    stage(1);

#pragma unroll 1
    for (int ch = 0; ch < NCHUNK; ch++) {
        if (ch + 2 < NCHUNK)
            asm volatile("cp.async.wait_group 1;\n" ::: "memory");
        else
            asm volatile("cp.async.wait_group 0;\n" ::: "memory");
        __syncthreads();

        const float* bp = sm + (ch % 3) * BUF_FLOATS;
        const float* tb = bp + t_off;
        const float* sb = bp + s_off;
#pragma unroll
        for (int cc = 0; cc < CCHUNK; cc++) {
            const float4* sp4 = (const float4*)(sb + cc * (YB * TX));
            const float4 s0 = sp4[0], s1 = sp4[1];
            const float4* tp4 = (const float4*)(tb + cc * (TGT_H * TGT_W));
            const float4 t0 = tp4[0], t1 = tp4[1], t2 = tp4[2], t3 = tp4[3];

            float tt[16] = {t0.x, t0.y, t0.z, t0.w, t1.x, t1.y, t1.z, t1.w,
                            t2.x, t2.y, t2.z, t2.w, t3.x, t3.y, t3.z, t3.w};
            ull sp[4] = {pk2(s0.x, s0.y), pk2(s0.z, s0.w),
                         pk2(s1.x, s1.y), pk2(s1.z, s1.w)};
            ull ap[8], sh[7];
#pragma unroll
            for (int i = 0; i < 8; i++) ap[i] = pk2(tt[2 * i], tt[2 * i + 1]);
#pragma unroll
            for (int i = 0; i < 7; i++) sh[i] = pk2(tt[2 * i + 1], tt[2 * i + 2]);

#pragma unroll
            for (int e = 0; e < 5; e++)       // dx = 0,2,4,6,8
#pragma unroll
                for (int j = 0; j < 4; j++)
                    fma2(acc[2 * e][j], sp[j], ap[e + j]);
#pragma unroll
            for (int o = 0; o < 4; o++)       // dx = 1,3,5,7
#pragma unroll
                for (int j = 0; j < 4; j++)
                    fma2(acc[2 * o + 1][j], sp[j], sh[o + j]);
        }

        if (ch + 2 < NCHUNK)
            stage((ch + 2) % 3);
    }

    // ---- epilogue: unpack, scale, scatter ----
    const float inv = 1.0f / 81.0f;
    const int y = y0 + yr;
#pragma unroll
    for (int dx = 0; dx < NDY; dx++) {
        int d = disp_index(dyv, dx - RR);
        float* o = out + ((((size_t)b * ND + d) * NH) + y) * NW + x0 + xg * PX;
        float a[8];
#pragma unroll
        for (int j = 0; j < 4; j++) upk2(acc[dx][j], a[2 * j], a[2 * j + 1]);
        float4 v0 = make_float4(a[0] * inv, a[1] * inv, a[2] * inv, a[3] * inv);
        float4 v1 = make_float4(a[4] * inv, a[5] * inv, a[6] * inv, a[7] * inv);
        *(float4*)o = v0;
        *((float4*)o + 1) = v1;
    }
}

extern "C" void kernel_launch(void* const* d_in, const int* in_sizes, int n_in,
                              void* d_out, int out_size) {
    const float* src = (const float*)d_in[0];
    const float* tgt = (const float*)d_in[1];
    float* out = (float*)d_out;

    cudaFuncSetAttribute(costvol_kernel,
                         cudaFuncAttributeMaxDynamicSharedMemorySize, SMEM_BYTES);

    dim3 grid(NW / TX, NH / YB, NB);   // (5, 12, 4) = 240 blocks -> single wave @ occ 2
    dim3 block(NTHREADS);              // 288 threads = 9 warps
    costvol_kernel<<<grid, block, SMEM_BYTES>>>(src, tgt, out);
}

// round 6
// speedup vs baseline: 1.1049x; 1.1049x over previous
#include <cuda_runtime.h>
#include <cstdint>

// Problem constants
#define RR 4
#define ND 81
#define NB 4
#define NC 128
#define NH 96
#define NW 160

// Tiling (R4 geometry)
#define TX 32
#define YB 4
#define PX 4
#define XG 8
#define NDY 9
#define NTHREADS 288          // 9 warps
#define CCHUNK 8
#define NCHUNK 16
#define TGT_W 40              // TX + 2*RR (packed, no padding; conflict-free by phase layout)
#define TGT_H 12              // YB + 2*RR
#define TGT_TILE (CCHUNK*TGT_H*TGT_W)   // 3840 floats
#define BUF_BYTES (TGT_TILE*4)          // 15360
#define SMEM_BYTES (3*BUF_BYTES)        // 46080
#define NQUADS (TGT_TILE/4)             // 960 = 3*288 + 96
#define MAXSLOTS 4
#define CBYTES (CCHUNK*NH*NW*4)

typedef unsigned long long ull;

__device__ __forceinline__ int disp_index(int dyv, int dxv) {
    int ay = dyv < 0 ? -dyv : dyv;
    int ax = dxv < 0 ? -dxv : dxv;
    if ((ay | ax) == 0) return 0;
    if (ax == 0) return 1 + (ay - 1) * 20 + (dyv < 0 ? 0 : 1);
    if (ay == 0) return 1 + (ax - 1) * 20 + (dxv < 0 ? 2 : 3);
    int base = 1 + (ay - 1) * 20 + 4 + (ax - 1) * 4;
    if (dyv < 0 && dxv < 0) return base + 0;
    if (dyv > 0 && dxv > 0) return base + 1;
    if (dyv < 0 && dxv > 0) return base + 2;
    return base + 3;
}

__device__ __forceinline__ void cp_async16(uint32_t saddr, const void* gaddr, int sz) {
    asm volatile("cp.async.cg.shared.global [%0], [%1], 16, %2;\n"
                 :: "r"(saddr), "l"(gaddr), "r"(sz));
}
__device__ __forceinline__ void cp_commit() {
    asm volatile("cp.async.commit_group;\n" ::: "memory");
}
__device__ __forceinline__ ull pk2(float lo, float hi) {
    ull r;
    asm("mov.b64 %0, {%1, %2};" : "=l"(r) : "f"(lo), "f"(hi));
    return r;
}
__device__ __forceinline__ void upk2(ull v, float& lo, float& hi) {
    asm("mov.b64 {%0, %1}, %2;" : "=f"(lo), "=f"(hi) : "l"(v));
}
__device__ __forceinline__ void fma2(ull& d, ull a, ull b) {
    asm("fma.rn.f32x2 %0, %1, %2, %0;" : "+l"(d) : "l"(a), "l"(b));
}

__global__ __launch_bounds__(NTHREADS, 3)
void costvol_kernel(const float* __restrict__ src,
                    const float* __restrict__ tgt,
                    float* __restrict__ out) {
    extern __shared__ __align__(16) float sm[];   // 3 * TGT_TILE

    const int tid = threadIdx.x;
    const int x0 = blockIdx.x * TX;
    const int y0 = blockIdx.y * YB;
    const int b  = blockIdx.z;

    const char* tgtB = (const char*)(tgt + (size_t)b * NC * NH * NW);

    // ---- tgt staging slots: quad idx = tid + k*288, smem offset = idx*16 ----
    uint32_t goff[MAXSLOTS];
    uint32_t flags = 0;     // bit k: in-bounds
#pragma unroll
    for (int k = 0; k < MAXSLOTS; k++) {
        int idx = tid + k * NTHREADS;
        goff[k] = 0;
        if (idx < NQUADS) {
            int cc  = idx / (TGT_H * (TGT_W / 4));   // /120
            int rem = idx % (TGT_H * (TGT_W / 4));
            int row = rem / (TGT_W / 4);             // /10
            int xq  = rem % (TGT_W / 4);
            int gy = y0 + row - RR;
            int gx = x0 + xq * 4 - RR;
            bool ok = ((unsigned)gy < NH) && ((unsigned)gx < NW);
            if (ok) {
                goff[k] = (uint32_t)(((cc * NH + gy) * NW + gx) * 4);
                flags |= 1u << k;
            }
        }
    }

    const uint32_t smem_base = (uint32_t)__cvta_generic_to_shared(&sm[0]);

    // ---- compute role ----
    const int xg   = tid & (XG - 1);
    const int dyi  = (tid >> 3) % NDY;
    const int yr   = tid / (XG * NDY);
    const int dyv  = dyi - RR;
    const int trow = yr + dyi;                      // 0..11
    const int t_off = trow * TGT_W + xg * PX;       // floats (16B aligned)

    // src read pointer: this thread's 4 pixels, channel 0; advances per channel
    const char* srcp = (const char*)(src +
        ((size_t)b * NC * NH * NW + (size_t)(y0 + yr) * NW + x0 + xg * PX));
    // note: pointer math above is in floats; convert to bytes:
    srcp = (const char*)src + ((size_t)b * NC * NH * NW
                               + (size_t)(y0 + yr) * NW + x0 + xg * PX) * 4;

    // accumulators: even dx as pairs, odd dx as mid-pair + 2 scalars
    ull acc_e[5][2];     // dx = 0,2,4,6,8 ; [0]=(p0,p1) [1]=(p2,p3)
    ull acc_m[4];        // dx = 1,3,5,7   ; (p1,p2)
    float acc_s[4][2];   // dx = 1,3,5,7   ; p0, p3
#pragma unroll
    for (int e = 0; e < 5; e++) { acc_e[e][0] = 0ull; acc_e[e][1] = 0ull; }
#pragma unroll
    for (int o = 0; o < 4; o++) { acc_m[o] = 0ull; acc_s[o][0] = 0.0f; acc_s[o][1] = 0.0f; }

    auto stage = [&](int bi) {
        const uint32_t bofs = (uint32_t)bi * BUF_BYTES;
#pragma unroll
        for (int k = 0; k < MAXSLOTS; k++) {
            if (k < MAXSLOTS - 1 || tid < NQUADS - (MAXSLOTS - 1) * NTHREADS) {
                int sz = (flags >> k & 1) ? 16 : 0;
                cp_async16(smem_base + bofs + (uint32_t)(tid + k * NTHREADS) * 16,
                           tgtB + goff[k], sz);
                goff[k] += CBYTES;
            }
        }
        cp_commit();
    };

    stage(0);
    stage(1);

#pragma unroll 1
    for (int ch = 0; ch < NCHUNK; ch++) {
        if (ch + 2 < NCHUNK)
            asm volatile("cp.async.wait_group 1;\n" ::: "memory");
        else
            asm volatile("cp.async.wait_group 0;\n" ::: "memory");
        __syncthreads();

        const float* bp = sm + (ch % 3) * TGT_TILE;
#pragma unroll
        for (int cc = 0; cc < CCHUNK; cc++) {
            // src: one 16B global load (L1-hit after first dyi touches it)
            const ulonglong2 sv =
                *(const ulonglong2*)(srcp + (size_t)cc * (NH * NW * 4));
            // tgt: 3 x 16B shared loads as native 64-bit pairs
            const ulonglong2* tq =
                (const ulonglong2*)(bp + t_off + cc * (TGT_H * TGT_W));
            const ulonglong2 tA = tq[0], tB = tq[1], tC = tq[2];
            const ull tp0 = tA.x, tp1 = tA.y, tp2 = tB.x,
                      tp3 = tB.y, tp4 = tC.x, tp5 = tC.y;

            float s0, s1, s2, s3;
            upk2(sv.x, s0, s1);
            upk2(sv.y, s2, s3);
            const ull s12 = pk2(s1, s2);   // the single real pack per channel

            // even dx = 2e : fully paired
            fma2(acc_e[0][0], sv.x, tp0);  fma2(acc_e[0][1], sv.y, tp1);
            fma2(acc_e[1][0], sv.x, tp1);  fma2(acc_e[1][1], sv.y, tp2);
            fma2(acc_e[2][0], sv.x, tp2);  fma2(acc_e[2][1], sv.y, tp3);
            fma2(acc_e[3][0], sv.x, tp3);  fma2(acc_e[3][1], sv.y, tp4);
            fma2(acc_e[4][0], sv.x, tp4);  fma2(acc_e[4][1], sv.y, tp5);

            // odd dx = 2o+1 : middle pair (p1,p2) uses aligned tgt pair tp[o+1]
            fma2(acc_m[0], s12, tp1);
            fma2(acc_m[1], s12, tp2);
            fma2(acc_m[2], s12, tp3);
            fma2(acc_m[3], s12, tp4);

            // odd dx scalar ends: p0 -> t[2o+1] (hi of tp[o]), p3 -> t[2o+4] (lo of tp[o+2])
            {
                float lo, hi;
                upk2(tp0, lo, hi); acc_s[0][0] = fmaf(s0, hi, acc_s[0][0]);
                upk2(tp1, lo, hi); acc_s[1][0] = fmaf(s0, hi, acc_s[1][0]);
                upk2(tp2, lo, hi); acc_s[2][0] = fmaf(s0, hi, acc_s[2][0]);
                                   acc_s[0][1] = fmaf(s3, lo, acc_s[0][1]);
                upk2(tp3, lo, hi); acc_s[3][0] = fmaf(s0, hi, acc_s[3][0]);
                                   acc_s[1][1] = fmaf(s3, lo, acc_s[1][1]);
                upk2(tp4, lo, hi); acc_s[2][1] = fmaf(s3, lo, acc_s[2][1]);
                upk2(tp5, lo, hi); acc_s[3][1] = fmaf(s3, lo, acc_s[3][1]);
            }
        }
        srcp += CBYTES;

        if (ch + 2 < NCHUNK)
            stage((ch + 2) % 3);
    }

    // ---- epilogue: unpack, scale, scatter ----
    const float inv = 1.0f / 81.0f;
    const int y = y0 + yr;
#pragma unroll
    for (int dx = 0; dx < NDY; dx++) {
        int d = disp_index(dyv, dx - RR);
        float a0, a1, a2, a3;
        if ((dx & 1) == 0) {
            int e = dx >> 1;
            upk2(acc_e[e][0], a0, a1);
            upk2(acc_e[e][1], a2, a3);
        } else {
            int o = dx >> 1;
            a0 = acc_s[o][0];
            upk2(acc_m[o], a1, a2);
            a3 = acc_s[o][1];
        }
        float* o = out + ((((size_t)b * ND + d) * NH) + y) * NW + x0 + xg * PX;
        *(float4*)o = make_float4(a0 * inv, a1 * inv, a2 * inv, a3 * inv);
    }
}

extern "C" void kernel_launch(void* const* d_in, const int* in_sizes, int n_in,
                              void* d_out, int out_size) {
    const float* src = (const float*)d_in[0];
    const float* tgt = (const float*)d_in[1];
    float* out = (float*)d_out;

    cudaFuncSetAttribute(costvol_kernel,
                         cudaFuncAttributeMaxDynamicSharedMemorySize, SMEM_BYTES);

    dim3 grid(NW / TX, NH / YB, NB);   // (5, 24, 4) = 480 blocks
    dim3 block(NTHREADS);              // 288 threads
    costvol_kernel<<<grid, block, SMEM_BYTES>>>(src, tgt, out);
}

// round 7
// speedup vs baseline: 1.2522x; 1.1333x over previous
#include <cuda_runtime.h>
#include <cstdint>

// Problem constants
#define RR 4
#define ND 81
#define NB 4
#define NC 128
#define NH 96
#define NW 160

// Tiling (R4 geometry)
#define TX 32
#define YB 4
#define PX 4
#define XG 8
#define NDY 9
#define NTHREADS 288          // 9 warps
#define CCHUNK 8
#define NCHUNK 16
#define TGT_W 40              // TX + 2*RR, packed
#define TGT_H 12              // YB + 2*RR
#define TGT_TILE (CCHUNK*TGT_H*TGT_W)    // 3840 floats
#define SRC_TILE (CCHUNK*YB*TX)          // 1024 floats
#define BUF_FLOATS (TGT_TILE + SRC_TILE) // 4864
#define BUF_BYTES (BUF_FLOATS*4)         // 19456
#define SMEM_BYTES (3*BUF_BYTES)         // 58368
#define NQUADS (BUF_FLOATS/4)            // 1216 = 4*288 + 64
#define MAXSLOTS 5
#define CBYTES (CCHUNK*NH*NW*4)

typedef unsigned long long ull;

__device__ __forceinline__ int disp_index(int dyv, int dxv) {
    int ay = dyv < 0 ? -dyv : dyv;
    int ax = dxv < 0 ? -dxv : dxv;
    if ((ay | ax) == 0) return 0;
    if (ax == 0) return 1 + (ay - 1) * 20 + (dyv < 0 ? 0 : 1);
    if (ay == 0) return 1 + (ax - 1) * 20 + (dxv < 0 ? 2 : 3);
    int base = 1 + (ay - 1) * 20 + 4 + (ax - 1) * 4;
    if (dyv < 0 && dxv < 0) return base + 0;
    if (dyv > 0 && dxv > 0) return base + 1;
    if (dyv < 0 && dxv > 0) return base + 2;
    return base + 3;
}

__device__ __forceinline__ void cp_async16(uint32_t saddr, const void* gaddr, int sz) {
    asm volatile("cp.async.cg.shared.global [%0], [%1], 16, %2;\n"
                 :: "r"(saddr), "l"(gaddr), "r"(sz));
}
__device__ __forceinline__ void cp_commit() {
    asm volatile("cp.async.commit_group;\n" ::: "memory");
}
__device__ __forceinline__ ull pk2(float lo, float hi) {
    ull r;
    asm("mov.b64 %0, {%1, %2};" : "=l"(r) : "f"(lo), "f"(hi));
    return r;
}
__device__ __forceinline__ void upk2(ull v, float& lo, float& hi) {
    asm("mov.b64 {%0, %1}, %2;" : "=f"(lo), "=f"(hi) : "l"(v));
}
__device__ __forceinline__ void fma2(ull& d, ull a, ull b) {
    asm("fma.rn.f32x2 %0, %1, %2, %0;" : "+l"(d) : "l"(a), "l"(b));
}

__global__ __launch_bounds__(NTHREADS, 3)
void costvol_kernel(const float* __restrict__ src,
                    const float* __restrict__ tgt,
                    float* __restrict__ out) {
    extern __shared__ __align__(16) float sm[];   // 3 * BUF_FLOATS

    const int tid = threadIdx.x;
    const int x0 = blockIdx.x * TX;
    const int y0 = blockIdx.y * YB;
    const int b  = blockIdx.z;

    const char* srcB = (const char*)(src + (size_t)b * NC * NH * NW);
    const char* tgtB = (const char*)(tgt + (size_t)b * NC * NH * NW);

    // ---- staging slots: quad idx = tid + k*288, smem byte off = idx*16 ----
    uint32_t goff[MAXSLOTS];
    uint32_t flags = 0;   // bit k: tgt slot; bit k+8: in-bounds
#pragma unroll
    for (int k = 0; k < MAXSLOTS; k++) {
        int idx = tid + k * NTHREADS;
        goff[k] = 0;
        if (idx < NQUADS) {
            if (idx < TGT_TILE / 4) {
                int cc  = idx / (TGT_H * (TGT_W / 4));   // /120
                int rem = idx % (TGT_H * (TGT_W / 4));
                int row = rem / (TGT_W / 4);             // /10
                int xq  = rem % (TGT_W / 4);
                int gy = y0 + row - RR;
                int gx = x0 + xq * 4 - RR;
                bool ok = ((unsigned)gy < NH) && ((unsigned)gx < NW);
                if (ok) goff[k] = (uint32_t)(((cc * NH + gy) * NW + gx) * 4);
                flags |= 1u << k;
                if (ok) flags |= 1u << (k + 8);
            } else {
                int q   = idx - TGT_TILE / 4;
                int cc  = q / (YB * TX / 4);             // /32
                int rem = q % (YB * TX / 4);
                int ry  = rem / (TX / 4);
                int xq  = rem % (TX / 4);
                goff[k] = (uint32_t)(((cc * NH + y0 + ry) * NW + x0 + xq * 4) * 4);
                flags |= 1u << (k + 8);
            }
        }
    }

    const uint32_t smem_base = (uint32_t)__cvta_generic_to_shared(&sm[0]);

    // ---- compute role ----
    const int xg   = tid & (XG - 1);
    const int dyi  = (tid >> 3) % NDY;
    const int yr   = tid / (XG * NDY);
    const int dyv  = dyi - RR;
    const int trow = yr + dyi;                       // 0..11
    const int t_off = trow * TGT_W + xg * PX;        // 16B-aligned
    const int s_off = TGT_TILE + yr * TX + xg * PX;  // 16B-aligned

    // accumulators: even dx fully paired, odd dx mid-pair + 2 scalars
    ull acc_e[5][2];     // dx = 0,2,4,6,8 : (p0,p1),(p2,p3)
    ull acc_m[4];        // dx = 1,3,5,7   : (p1,p2)
    float acc_s[4][2];   // dx = 1,3,5,7   : p0, p3
#pragma unroll
    for (int e = 0; e < 5; e++) { acc_e[e][0] = 0ull; acc_e[e][1] = 0ull; }
#pragma unroll
    for (int o = 0; o < 4; o++) { acc_m[o] = 0ull; acc_s[o][0] = 0.0f; acc_s[o][1] = 0.0f; }

    auto stage = [&](int bi) {
        const uint32_t bofs = (uint32_t)bi * BUF_BYTES;
#pragma unroll
        for (int k = 0; k < MAXSLOTS; k++) {
            if (k < MAXSLOTS - 1 || tid < NQUADS - (MAXSLOTS - 1) * NTHREADS) {
                const char* base = (flags >> k & 1) ? tgtB : srcB;
                int sz = (flags >> (k + 8) & 1) ? 16 : 0;
                cp_async16(smem_base + bofs + (uint32_t)(tid + k * NTHREADS) * 16,
                           base + goff[k], sz);
                goff[k] += CBYTES;
            }
        }
        cp_commit();
    };

    stage(0);
    stage(1);

#pragma unroll 1
    for (int ch = 0; ch < NCHUNK; ch++) {
        if (ch + 2 < NCHUNK)
            asm volatile("cp.async.wait_group 1;\n" ::: "memory");
        else
            asm volatile("cp.async.wait_group 0;\n" ::: "memory");
        __syncthreads();

        const float* bp = sm + (ch % 3) * BUF_FLOATS;
        const float* tb = bp + t_off;
        const float* sb = bp + s_off;
#pragma unroll
        for (int cc = 0; cc < CCHUNK; cc++) {
            // src: one LDS.128 as two native 64-bit pairs
            const ulonglong2 sv = *(const ulonglong2*)(sb + cc * (YB * TX));
            // tgt: 3 LDS.128 -> 6 native pairs
            const ulonglong2* tq =
                (const ulonglong2*)(tb + cc * (TGT_H * TGT_W));
            const ulonglong2 tA = tq[0], tB = tq[1], tC = tq[2];
            const ull tp0 = tA.x, tp1 = tA.y, tp2 = tB.x,
                      tp3 = tB.y, tp4 = tC.x, tp5 = tC.y;

            float s0, s1, s2, s3;
            upk2(sv.x, s0, s1);
            upk2(sv.y, s2, s3);
            const ull s12 = pk2(s1, s2);   // single real pack per channel

            // even dx = 0,2,4,6,8 : fully paired
            fma2(acc_e[0][0], sv.x, tp0);  fma2(acc_e[0][1], sv.y, tp1);
            fma2(acc_e[1][0], sv.x, tp1);  fma2(acc_e[1][1], sv.y, tp2);
            fma2(acc_e[2][0], sv.x, tp2);  fma2(acc_e[2][1], sv.y, tp3);
            fma2(acc_e[3][0], sv.x, tp3);  fma2(acc_e[3][1], sv.y, tp4);
            fma2(acc_e[4][0], sv.x, tp4);  fma2(acc_e[4][1], sv.y, tp5);

            // odd dx = 1,3,5,7 : middle pair (p1,p2) x aligned tgt pair
            fma2(acc_m[0], s12, tp1);
            fma2(acc_m[1], s12, tp2);
            fma2(acc_m[2], s12, tp3);
            fma2(acc_m[3], s12, tp4);

            // odd dx scalar ends: p0 * t[2o+1] (hi of tp[o]); p3 * t[2o+4] (lo of tp[o+2])
            {
                float lo, hi;
                upk2(tp0, lo, hi); acc_s[0][0] = fmaf(s0, hi, acc_s[0][0]);
                upk2(tp1, lo, hi); acc_s[1][0] = fmaf(s0, hi, acc_s[1][0]);
                upk2(tp2, lo, hi); acc_s[2][0] = fmaf(s0, hi, acc_s[2][0]);
                                   acc_s[0][1] = fmaf(s3, lo, acc_s[0][1]);
                upk2(tp3, lo, hi); acc_s[3][0] = fmaf(s0, hi, acc_s[3][0]);
                                   acc_s[1][1] = fmaf(s3, lo, acc_s[1][1]);
                upk2(tp4, lo, hi); acc_s[2][1] = fmaf(s3, lo, acc_s[2][1]);
                upk2(tp5, lo, hi); acc_s[3][1] = fmaf(s3, lo, acc_s[3][1]);
            }
        }

        if (ch + 2 < NCHUNK)
            stage((ch + 2) % 3);
    }

    // ---- epilogue: unpack, scale, scatter ----
    const float inv = 1.0f / 81.0f;
    const int y = y0 + yr;
#pragma unroll
    for (int dx = 0; dx < NDY; dx++) {
        int d = disp_index(dyv, dx - RR);
        float a0, a1, a2, a3;
        if ((dx & 1) == 0) {
            int e = dx >> 1;
            upk2(acc_e[e][0], a0, a1);
            upk2(acc_e[e][1], a2, a3);
        } else {
            int o = dx >> 1;
            a0 = acc_s[o][0];
            upk2(acc_m[o], a1, a2);
            a3 = acc_s[o][1];
        }
        float* o = out + ((((size_t)b * ND + d) * NH) + y) * NW + x0 + xg * PX;
        *(float4*)o = make_float4(a0 * inv, a1 * inv, a2 * inv, a3 * inv);
    }
}

extern "C" void kernel_launch(void* const* d_in, const int* in_sizes, int n_in,
                              void* d_out, int out_size) {
    const float* src = (const float*)d_in[0];
    const float* tgt = (const float*)d_in[1];
    float* out = (float*)d_out;

    cudaFuncSetAttribute(costvol_kernel,
                         cudaFuncAttributeMaxDynamicSharedMemorySize, SMEM_BYTES);

    dim3 grid(NW / TX, NH / YB, NB);   // (5, 24, 4) = 480 blocks
    dim3 block(NTHREADS);              // 288 threads
    costvol_kernel<<<grid, block, SMEM_BYTES>>>(src, tgt, out);
}